// round 3
// baseline (speedup 1.0000x reference)
#include <cuda_runtime.h>
#include <cuda_bf16.h>

// Problem constants
#define KK 8      // slots
#define VV 256    // vocab
#define TT 11     // time
#define NN 8      // scanner neurons
#define HH 255    // hidden per slot
#define BB 2048   // batch

// Precomputed per-(k,v) contribution to the two output channels.
// 8*256 float2 = 16 KB. __device__ global (no allocation allowed).
__device__ float2 g_table[KK * VV];

// ----------------------------------------------------------------------------
// Kernel 1: build G[o,k,v] = sum_h out_w[o, k*255+h] *
//                            relu( sum_n hidden_w[k*255+h, n] * relu(scanner_w[n,v,k]) )
// One warp per (k, v). Lanes split the 255 hidden neurons.
// ----------------------------------------------------------------------------
__global__ void precompute_table(const float* __restrict__ scanner_w,   // (N, V, K)
                                 const float* __restrict__ hidden_w,    // (K*H, N)
                                 const float* __restrict__ out_w) {     // (2, K*H)
    int warp = (blockIdx.x * blockDim.x + threadIdx.x) >> 5;
    int lane = threadIdx.x & 31;
    if (warp >= KK * VV) return;
    int k = warp >> 8;      // 0..7
    int v = warp & 255;     // 0..255

    // s_n = relu(scanner_w[n, v, k])
    float s[NN];
#pragma unroll
    for (int n = 0; n < NN; n++) {
        float w = __ldg(&scanner_w[n * (VV * KK) + v * KK + k]);
        s[n] = w > 0.f ? w : 0.f;
    }

    float g0 = 0.f, g1 = 0.f;
#pragma unroll
    for (int j = 0; j < 8; j++) {
        int h = lane + j * 32;
        if (h < HH) {
            int c = k * HH + h;
            const float4* hw = (const float4*)(hidden_w + c * NN);
            float4 w0 = hw[0];
            float4 w1 = hw[1];
            float acc = w0.x * s[0] + w0.y * s[1] + w0.z * s[2] + w0.w * s[3]
                      + w1.x * s[4] + w1.y * s[5] + w1.z * s[6] + w1.w * s[7];
            float a = acc > 0.f ? acc : 0.f;
            g0 = fmaf(a, __ldg(&out_w[c]), g0);
            g1 = fmaf(a, __ldg(&out_w[KK * HH + c]), g1);
        }
    }
    // warp reduce (fixed order -> deterministic)
#pragma unroll
    for (int off = 16; off > 0; off >>= 1) {
        g0 += __shfl_xor_sync(0xffffffffu, g0, off);
        g1 += __shfl_xor_sync(0xffffffffu, g1, off);
    }
    if (lane == 0) g_table[k * VV + v] = make_float2(g0, g1);
}

// ----------------------------------------------------------------------------
// Kernel 2: stream x_unfolded (B, V, T, K) once.
// Inner (t,k) block is 88 contiguous floats per (b,v). One thread owns one
// float4 chunk (tk4 in [0,22)) and scans all 256 v values (stride 88 floats).
// Consecutive threads -> consecutive float4s -> fully coalesced warps.
// One-hot index recovered by fid = fma(val, (float)v, fid); val sum tracked
// as the multiplier (exactly 1.0 for jax one_hot).
// Units = B*22 = 45056 = 704 blocks * 64 threads.
// ----------------------------------------------------------------------------
__global__ void __launch_bounds__(64)
scanner_stream(const float* __restrict__ x,
               const float* __restrict__ out_bias,   // (2,)
               float* __restrict__ out) {            // (B, 2, T)
    int u = blockIdx.x * blockDim.x + threadIdx.x;   // u = b*22 + tk4
    int b = u / 22;
    int tk4 = u - b * 22;

    const float4* base = (const float4*)(x + (size_t)b * (VV * TT * KK)) + tk4;

    float f0 = 0.f, f1 = 0.f, f2 = 0.f, f3 = 0.f;   // index accumulators
    float w0 = 0.f, w1 = 0.f, w2 = 0.f, w3 = 0.f;   // one-hot value accumulators
    float vf = 0.f;
#pragma unroll 8
    for (int v = 0; v < VV; v++) {
        float4 val = __ldcs(&base[v * 22]);          // 352B stride, evict-first
        f0 = fmaf(val.x, vf, f0);  w0 += val.x;
        f1 = fmaf(val.y, vf, f1);  w1 += val.y;
        f2 = fmaf(val.z, vf, f2);  w2 += val.z;
        f3 = fmaf(val.w, vf, f3);  w3 += val.w;
        vf += 1.f;
    }

    int tk    = tk4 * 4;         // first of 4 consecutive (t,k) pairs (same t)
    int t     = tk >> 3;
    int kbase = tk & 7;          // 0 or 4

    float s0 = 0.f, s1 = 0.f;
    int id;
    float2 g;
    id = (int)(f0 + 0.5f); g = g_table[(kbase + 0) * VV + id];
    s0 = fmaf(w0, g.x, s0); s1 = fmaf(w0, g.y, s1);
    id = (int)(f1 + 0.5f); g = g_table[(kbase + 1) * VV + id];
    s0 = fmaf(w1, g.x, s0); s1 = fmaf(w1, g.y, s1);
    id = (int)(f2 + 0.5f); g = g_table[(kbase + 2) * VV + id];
    s0 = fmaf(w2, g.x, s0); s1 = fmaf(w2, g.y, s1);
    id = (int)(f3 + 0.5f); g = g_table[(kbase + 3) * VV + id];
    s0 = fmaf(w3, g.x, s0); s1 = fmaf(w3, g.y, s1);

    // merge k=0..3 half with k=4..7 half (adjacent lanes, same t)
    s0 += __shfl_xor_sync(0xffffffffu, s0, 1);
    s1 += __shfl_xor_sync(0xffffffffu, s1, 1);

    if ((u & 1) == 0) {
        float b0 = __ldg(&out_bias[0]);
        float b1 = __ldg(&out_bias[1]);
        out[b * (2 * TT) + t]      = s0 + b0;
        out[b * (2 * TT) + TT + t] = s1 + b1;
    }
}

extern "C" void kernel_launch(void* const* d_in, const int* in_sizes, int n_in,
                              void* d_out, int out_size) {
    const float* x         = (const float*)d_in[0];   // (B, V, T, K)  46137344
    const float* scanner_w = (const float*)d_in[1];   // (N, V, K)     16384
    const float* hidden_w  = (const float*)d_in[2];   // (K*H, N)      16320
    const float* out_w     = (const float*)d_in[3];   // (2, K*H)      4080
    const float* out_bias  = (const float*)d_in[4];   // (2,)          2
    float* out = (float*)d_out;                       // (B, 2, T)     45056

    // 2048 warps, 8 warps/block
    precompute_table<<<256, 256>>>(scanner_w, hidden_w, out_w);
    // 45056 units, 64-thread blocks for low wave imbalance
    scanner_stream<<<704, 64>>>(x, out_bias, out);
}

// round 5
// speedup vs baseline: 1.7057x; 1.7057x over previous
#include <cuda_runtime.h>
#include <cuda_bf16.h>

// Problem constants
#define KK 8      // slots
#define VV 256    // vocab
#define TT 11     // time
#define NN 8      // scanner neurons
#define HH 255    // hidden per slot
#define BB 2048   // batch

#define VS 8              // v segments per batch element
#define VLEN (VV / VS)    // 32 v values per segment
#define TK4 22            // float4 chunks per (b, v): 88 floats / 4

// Precomputed per-(k,v) contribution to the two output channels.
// 8*256 float2 = 16 KB. __device__ global (no allocation allowed).
__device__ float2 g_table[KK * VV];

// ----------------------------------------------------------------------------
// Kernel 1: build G[o,k,v] = sum_h out_w[o, k*255+h] *
//                            relu( sum_n hidden_w[k*255+h, n] * relu(scanner_w[n,v,k]) )
// One warp per (k, v). Lanes split the 255 hidden neurons.
// ----------------------------------------------------------------------------
__global__ void precompute_table(const float* __restrict__ scanner_w,   // (N, V, K)
                                 const float* __restrict__ hidden_w,    // (K*H, N)
                                 const float* __restrict__ out_w) {     // (2, K*H)
    int warp = (blockIdx.x * blockDim.x + threadIdx.x) >> 5;
    int lane = threadIdx.x & 31;
    if (warp >= KK * VV) return;
    int k = warp >> 8;      // 0..7
    int v = warp & 255;     // 0..255

    float s[NN];
#pragma unroll
    for (int n = 0; n < NN; n++) {
        float w = __ldg(&scanner_w[n * (VV * KK) + v * KK + k]);
        s[n] = w > 0.f ? w : 0.f;
    }

    float g0 = 0.f, g1 = 0.f;
#pragma unroll
    for (int j = 0; j < 8; j++) {
        int h = lane + j * 32;
        if (h < HH) {
            int c = k * HH + h;
            const float4* hw = (const float4*)(hidden_w + c * NN);
            float4 w0 = hw[0];
            float4 w1 = hw[1];
            float acc = w0.x * s[0] + w0.y * s[1] + w0.z * s[2] + w0.w * s[3]
                      + w1.x * s[4] + w1.y * s[5] + w1.z * s[6] + w1.w * s[7];
            float a = acc > 0.f ? acc : 0.f;
            g0 = fmaf(a, __ldg(&out_w[c]), g0);
            g1 = fmaf(a, __ldg(&out_w[KK * HH + c]), g1);
        }
    }
#pragma unroll
    for (int off = 16; off > 0; off >>= 1) {
        g0 += __shfl_xor_sync(0xffffffffu, g0, off);
        g1 += __shfl_xor_sync(0xffffffffu, g1, off);
    }
    if (lane == 0) g_table[k * VV + v] = make_float2(g0, g1);
}

// ----------------------------------------------------------------------------
// Kernel 2: stream x_unfolded (B, V, T, K). One block per batch element b.
// 176 threads = 22 tk4-chunks x 8 v-segments. Each thread scans 32 v values
// of its float4 chunk (stride 88 floats), accumulating the one-hot index
// (f = sum val*v) and weight (w = sum val). Partials are summed across the
// 8 segments in shared memory (pure addition -> exact), then 22 threads do
// the table lookups and a lane-pair shuffle produces the 11 (t) outputs.
// ----------------------------------------------------------------------------
__global__ void __launch_bounds__(176)
scanner_stream(const float* __restrict__ x,
               const float* __restrict__ out_bias,   // (2,)
               float* __restrict__ out) {            // (B, 2, T)
    int b    = blockIdx.x;
    int tid  = threadIdx.x;          // 0..175
    int vseg = tid / TK4;            // 0..7
    int tk4  = tid - vseg * TK4;     // 0..21

    const float4* base = (const float4*)(x + (size_t)b * (VV * TT * KK))
                         + (size_t)vseg * VLEN * TK4 + tk4;

    float f0 = 0.f, f1 = 0.f, f2 = 0.f, f3 = 0.f;   // index accumulators
    float w0 = 0.f, w1 = 0.f, w2 = 0.f, w3 = 0.f;   // one-hot value accumulators
    float vf = (float)(vseg * VLEN);
#pragma unroll
    for (int i = 0; i < VLEN; i++) {
        float4 val = __ldcs(&base[i * TK4]);        // 352B stride, streaming
        f0 = fmaf(val.x, vf, f0);  w0 += val.x;
        f1 = fmaf(val.y, vf, f1);  w1 += val.y;
        f2 = fmaf(val.z, vf, f2);  w2 += val.z;
        f3 = fmaf(val.w, vf, f3);  w3 += val.w;
        vf += 1.f;
    }

    __shared__ float4 sf[VS][TK4];
    __shared__ float4 sw[VS][TK4];
    sf[vseg][tk4] = make_float4(f0, f1, f2, f3);
    sw[vseg][tk4] = make_float4(w0, w1, w2, w3);
    __syncthreads();

    if (tid < TK4) {                                 // lanes 0..21 of warp 0
        float4 F = sf[0][tid];
        float4 W = sw[0][tid];
#pragma unroll
        for (int s = 1; s < VS; s++) {
            float4 pf = sf[s][tid];
            float4 pw = sw[s][tid];
            F.x += pf.x; F.y += pf.y; F.z += pf.z; F.w += pf.w;
            W.x += pw.x; W.y += pw.y; W.z += pw.z; W.w += pw.w;
        }

        int t     = tid >> 1;            // 4 consecutive tk share one t
        int kbase = (tid & 1) * 4;       // 0 or 4

        float s0 = 0.f, s1 = 0.f;
        int id;
        float2 g;
        id = (int)(F.x + 0.5f); g = g_table[(kbase + 0) * VV + id];
        s0 = fmaf(W.x, g.x, s0); s1 = fmaf(W.x, g.y, s1);
        id = (int)(F.y + 0.5f); g = g_table[(kbase + 1) * VV + id];
        s0 = fmaf(W.y, g.x, s0); s1 = fmaf(W.y, g.y, s1);
        id = (int)(F.z + 0.5f); g = g_table[(kbase + 2) * VV + id];
        s0 = fmaf(W.z, g.x, s0); s1 = fmaf(W.z, g.y, s1);
        id = (int)(F.w + 0.5f); g = g_table[(kbase + 3) * VV + id];
        s0 = fmaf(W.w, g.x, s0); s1 = fmaf(W.w, g.y, s1);

        // merge k=0..3 half (even lane) with k=4..7 half (odd lane)
        const unsigned mask = 0x003FFFFFu;           // lanes 0..21
        s0 += __shfl_xor_sync(mask, s0, 1);
        s1 += __shfl_xor_sync(mask, s1, 1);

        if ((tid & 1) == 0) {
            out[b * (2 * TT) + t]      = s0 + __ldg(&out_bias[0]);
            out[b * (2 * TT) + TT + t] = s1 + __ldg(&out_bias[1]);
        }
    }
}

extern "C" void kernel_launch(void* const* d_in, const int* in_sizes, int n_in,
                              void* d_out, int out_size) {
    const float* x         = (const float*)d_in[0];   // (B, V, T, K)  46137344
    const float* scanner_w = (const float*)d_in[1];   // (N, V, K)     16384
    const float* hidden_w  = (const float*)d_in[2];   // (K*H, N)      16320
    const float* out_w     = (const float*)d_in[3];   // (2, K*H)      4080
    const float* out_bias  = (const float*)d_in[4];   // (2,)          2
    float* out = (float*)d_out;                       // (B, 2, T)     45056

    precompute_table<<<256, 256>>>(scanner_w, hidden_w, out_w);
    scanner_stream<<<BB, 176>>>(x, out_bias, out);
}

// round 8
// speedup vs baseline: 1.7579x; 1.0306x over previous
#include <cuda_runtime.h>
#include <cuda_bf16.h>

// Problem constants
#define KK 8      // slots
#define VV 256    // vocab
#define TT 11     // time
#define NN 8      // scanner neurons
#define HH 255    // hidden per slot
#define BB 2048   // batch

#define VS 8              // v segments per block
#define VLEN 16           // v values per thread
#define VHALF 128         // v values per block (2 blocks per batch element)
#define TK4 22            // float4 chunks per (b, v): 88 floats / 4

// Precomputed per-(k,v) contribution to the two output channels, with the
// output bias folded in as bias/8 per slot. 8*256 float2 = 16 KB.
__device__ float2 g_table[KK * VV];

// ----------------------------------------------------------------------------
// Kernel 1: build G'[o,k,v] = out_b[o]/8 + sum_h out_w[o, k*255+h] *
//               relu( sum_n hidden_w[k*255+h, n] * relu(scanner_w[n,v,k]) )
// One warp per (k, v). Also zero-initializes the output buffer (the stream
// kernel accumulates into it with atomics).
// ----------------------------------------------------------------------------
__global__ void precompute_table(const float* __restrict__ scanner_w,   // (N, V, K)
                                 const float* __restrict__ hidden_w,    // (K*H, N)
                                 const float* __restrict__ out_w,       // (2, K*H)
                                 const float* __restrict__ out_b,       // (2,)
                                 float* __restrict__ out) {             // (B, 2, T)
    int gtid = blockIdx.x * blockDim.x + threadIdx.x;   // 65536 threads
    if (gtid < BB * 2 * TT) out[gtid] = 0.f;            // zero-init for atomics

    int warp = gtid >> 5;
    int lane = threadIdx.x & 31;
    if (warp >= KK * VV) return;
    int k = warp >> 8;      // 0..7
    int v = warp & 255;     // 0..255

    float s[NN];
#pragma unroll
    for (int n = 0; n < NN; n++) {
        float w = __ldg(&scanner_w[n * (VV * KK) + v * KK + k]);
        s[n] = w > 0.f ? w : 0.f;
    }

    float g0 = 0.f, g1 = 0.f;
#pragma unroll
    for (int j = 0; j < 8; j++) {
        int h = lane + j * 32;
        if (h < HH) {
            int c = k * HH + h;
            const float4* hw = (const float4*)(hidden_w + c * NN);
            float4 w0 = hw[0];
            float4 w1 = hw[1];
            float acc = w0.x * s[0] + w0.y * s[1] + w0.z * s[2] + w0.w * s[3]
                      + w1.x * s[4] + w1.y * s[5] + w1.z * s[6] + w1.w * s[7];
            float a = acc > 0.f ? acc : 0.f;
            g0 = fmaf(a, __ldg(&out_w[c]), g0);
            g1 = fmaf(a, __ldg(&out_w[KK * HH + c]), g1);
        }
    }
#pragma unroll
    for (int off = 16; off > 0; off >>= 1) {
        g0 += __shfl_xor_sync(0xffffffffu, g0, off);
        g1 += __shfl_xor_sync(0xffffffffu, g1, off);
    }
    if (lane == 0) {
        // fold bias/8 into each slot entry (8 slots sum to exactly 1x bias)
        g_table[k * VV + v] = make_float2(g0 + 0.125f * __ldg(&out_b[0]),
                                          g1 + 0.125f * __ldg(&out_b[1]));
    }
}

// ----------------------------------------------------------------------------
// Kernel 2: stream x_unfolded (B, V, T, K). Two blocks per batch element,
// each covering 128 v values. 176 threads = 22 tk4-chunks x 8 v-segments;
// each thread scans 16 v values of its float4 chunk (stride 88 floats).
//
// One-hot structure: each (t,k) column has exactly one v with value 1.0, so
// a partial scan yields w in {0,1} and (when w=1) f = sum(val*i) recovers the
// index as id = f + vbase*w. Each thread does its own table lookups; the
// per-t partial sums reduce deterministically in smem, and the two blocks of
// a batch element combine via one atomicAdd each (2 commutative float adds
// onto a zeroed cell -> bit-deterministic).
// ----------------------------------------------------------------------------
__global__ void __launch_bounds__(176, 10)
scanner_stream(const float* __restrict__ x,
               float* __restrict__ out) {            // (B, 2, T)
    int b     = blockIdx.x >> 1;
    int vhalf = blockIdx.x & 1;
    int tid   = threadIdx.x;          // 0..175
    int vseg  = tid / TK4;            // 0..7
    int tk4   = tid - vseg * TK4;     // 0..21
    int vbase = vhalf * VHALF + vseg * VLEN;

    const float4* base = (const float4*)(x + (size_t)b * (VV * TT * KK))
                         + (size_t)vbase * TK4 + tk4;

    float f0 = 0.f, f1 = 0.f, f2 = 0.f, f3 = 0.f;   // sum val * i (i immediate)
    float w0 = 0.f, w1 = 0.f, w2 = 0.f, w3 = 0.f;   // sum val (0 or 1)
#pragma unroll
    for (int i = 0; i < VLEN; i++) {
        float4 val = __ldcs(&base[i * TK4]);        // 352B stride, streaming
        float fi = (float)i;                        // compile-time immediate
        f0 = fmaf(val.x, fi, f0);  w0 += val.x;
        f1 = fmaf(val.y, fi, f1);  w1 += val.y;
        f2 = fmaf(val.z, fi, f2);  w2 += val.z;
        f3 = fmaf(val.w, fi, f3);  w3 += val.w;
    }

    // per-thread table lookups (id exact: one-hot value is exactly 1.0)
    float vb = (float)vbase;
    int kbase = (tk4 & 1) * 4;       // even chunk -> k0..3, odd -> k4..7
    float s0 = 0.f, s1 = 0.f;
    int id;
    float2 g;
    id = (int)(fmaf(vb, w0, f0) + 0.5f); g = g_table[(kbase + 0) * VV + id];
    s0 = fmaf(w0, g.x, s0); s1 = fmaf(w0, g.y, s1);
    id = (int)(fmaf(vb, w1, f1) + 0.5f); g = g_table[(kbase + 1) * VV + id];
    s0 = fmaf(w1, g.x, s0); s1 = fmaf(w1, g.y, s1);
    id = (int)(fmaf(vb, w2, f2) + 0.5f); g = g_table[(kbase + 2) * VV + id];
    s0 = fmaf(w2, g.x, s0); s1 = fmaf(w2, g.y, s1);
    id = (int)(fmaf(vb, w3, f3) + 0.5f); g = g_table[(kbase + 3) * VV + id];
    s0 = fmaf(w3, g.x, s0); s1 = fmaf(w3, g.y, s1);

    __shared__ float2 ss[VS][TK4];
    ss[vseg][tk4] = make_float2(s0, s1);
    __syncthreads();

    if (tid < TK4) {                  // lanes 0..21 of warp 0
        float a0 = 0.f, a1 = 0.f;
#pragma unroll
        for (int s = 0; s < VS; s++) {   // fixed order -> deterministic
            float2 p = ss[s][tid];
            a0 += p.x; a1 += p.y;
        }
        // merge k0..3 half (even lane) with k4..7 half (odd lane)
        const unsigned mask = 0x003FFFFFu;
        a0 += __shfl_xor_sync(mask, a0, 1);
        a1 += __shfl_xor_sync(mask, a1, 1);

        if ((tid & 1) == 0) {
            int t = tid >> 1;
            atomicAdd(&out[b * (2 * TT) + t],      a0);
            atomicAdd(&out[b * (2 * TT) + TT + t], a1);
        }
    }
}

extern "C" void kernel_launch(void* const* d_in, const int* in_sizes, int n_in,
                              void* d_out, int out_size) {
    const float* x         = (const float*)d_in[0];   // (B, V, T, K)  46137344
    const float* scanner_w = (const float*)d_in[1];   // (N, V, K)     16384
    const float* hidden_w  = (const float*)d_in[2];   // (K*H, N)      16320
    const float* out_w     = (const float*)d_in[3];   // (2, K*H)      4080
    const float* out_bias  = (const float*)d_in[4];   // (2,)          2
    float* out = (float*)d_out;                       // (B, 2, T)     45056

    precompute_table<<<256, 256>>>(scanner_w, hidden_w, out_w, out_bias, out);
    scanner_stream<<<2 * BB, 176>>>(x, out);
}

// round 9
// speedup vs baseline: 1.8635x; 1.0601x over previous
#include <cuda_runtime.h>
#include <cuda_bf16.h>

// Problem constants
#define KK 8      // slots
#define VV 256    // vocab
#define TT 11     // time
#define NN 8      // scanner neurons
#define HH 255    // hidden per slot
#define BB 2048   // batch

#define VS 8              // v segments per block
#define VLEN 16           // v values per thread
#define VHALF 128         // v values per block (2 blocks per batch element)
#define TK4 22            // float4 chunks per (b, v): 88 floats / 4

// Precomputed per-(k,v) contribution to the two output channels, with the
// output bias folded in as bias/8 per slot. 8*256 float2 = 16 KB.
__device__ float2 g_table[KK * VV];

// ----------------------------------------------------------------------------
// Kernel 1 (PDL primary): build
//   G'[o,k,v] = out_b[o]/8 + sum_h out_w[o, k*255+h] *
//               relu( sum_n hidden_w[k*255+h, n] * relu(scanner_w[n,v,k]) )
// One warp per (k, v). Also zero-initializes the output buffer (the stream
// kernel accumulates into it with atomics). Triggers the dependent stream
// kernel's launch immediately — its epilogue grid-dep-syncs on us anyway.
// ----------------------------------------------------------------------------
__global__ void precompute_table(const float* __restrict__ scanner_w,   // (N, V, K)
                                 const float* __restrict__ hidden_w,    // (K*H, N)
                                 const float* __restrict__ out_w,       // (2, K*H)
                                 const float* __restrict__ out_b,       // (2,)
                                 float* __restrict__ out) {             // (B, 2, T)
    cudaTriggerProgrammaticLaunchCompletion();   // let the stream kernel ramp now

    int gtid = blockIdx.x * blockDim.x + threadIdx.x;   // 65536 threads
    if (gtid < BB * 2 * TT) out[gtid] = 0.f;            // zero-init for atomics

    int warp = gtid >> 5;
    int lane = threadIdx.x & 31;
    if (warp >= KK * VV) return;
    int k = warp >> 8;      // 0..7
    int v = warp & 255;     // 0..255

    float s[NN];
#pragma unroll
    for (int n = 0; n < NN; n++) {
        float w = __ldg(&scanner_w[n * (VV * KK) + v * KK + k]);
        s[n] = w > 0.f ? w : 0.f;
    }

    float g0 = 0.f, g1 = 0.f;
#pragma unroll
    for (int j = 0; j < 8; j++) {
        int h = lane + j * 32;
        if (h < HH) {
            int c = k * HH + h;
            const float4* hw = (const float4*)(hidden_w + c * NN);
            float4 w0 = hw[0];
            float4 w1 = hw[1];
            float acc = w0.x * s[0] + w0.y * s[1] + w0.z * s[2] + w0.w * s[3]
                      + w1.x * s[4] + w1.y * s[5] + w1.z * s[6] + w1.w * s[7];
            float a = acc > 0.f ? acc : 0.f;
            g0 = fmaf(a, __ldg(&out_w[c]), g0);
            g1 = fmaf(a, __ldg(&out_w[KK * HH + c]), g1);
        }
    }
#pragma unroll
    for (int off = 16; off > 0; off >>= 1) {
        g0 += __shfl_xor_sync(0xffffffffu, g0, off);
        g1 += __shfl_xor_sync(0xffffffffu, g1, off);
    }
    if (lane == 0) {
        // fold bias/8 into each slot entry (8 slots sum to exactly 1x bias)
        g_table[k * VV + v] = make_float2(g0 + 0.125f * __ldg(&out_b[0]),
                                          g1 + 0.125f * __ldg(&out_b[1]));
    }
}

// ----------------------------------------------------------------------------
// Kernel 2 (PDL secondary): stream x_unfolded (B, V, T, K). Two blocks per
// batch element, each covering 128 v values. 176 threads = 22 tk4-chunks x
// 8 v-segments; each thread scans 16 v values of its float4 chunk (stride 88
// floats). The DRAM-bound load loop runs BEFORE cudaGridDependencySynchronize,
// overlapping with the precompute kernel; only the table-lookup epilogue
// waits for it.
//
// One-hot structure: each (t,k) column has exactly one v with value 1.0, so
// a partial scan yields w in {0,1} and (when w=1) f = sum(val*i) recovers the
// index as id = f + vbase*w. Per-t partials reduce deterministically in smem;
// the two blocks of a batch element combine via one atomicAdd each (2
// commutative float adds onto a zeroed cell -> bit-deterministic).
// ----------------------------------------------------------------------------
__global__ void __launch_bounds__(176, 10)
scanner_stream(const float* __restrict__ x,
               float* __restrict__ out) {            // (B, 2, T)
    int b     = blockIdx.x >> 1;
    int vhalf = blockIdx.x & 1;
    int tid   = threadIdx.x;          // 0..175
    int vseg  = tid / TK4;            // 0..7
    int tk4   = tid - vseg * TK4;     // 0..21
    int vbase = vhalf * VHALF + vseg * VLEN;

    const float4* base = (const float4*)(x + (size_t)b * (VV * TT * KK))
                         + (size_t)vbase * TK4 + tk4;

    float f0 = 0.f, f1 = 0.f, f2 = 0.f, f3 = 0.f;   // sum val * i (i immediate)
    float w0 = 0.f, w1 = 0.f, w2 = 0.f, w3 = 0.f;   // sum val (0 or 1)
#pragma unroll
    for (int i = 0; i < VLEN; i++) {
        float4 val = __ldcs(&base[i * TK4]);        // 352B stride, streaming
        float fi = (float)i;                        // compile-time immediate
        f0 = fmaf(val.x, fi, f0);  w0 += val.x;
        f1 = fmaf(val.y, fi, f1);  w1 += val.y;
        f2 = fmaf(val.z, fi, f2);  w2 += val.z;
        f3 = fmaf(val.w, fi, f3);  w3 += val.w;
    }

    // Wait for precompute (g_table + out zero-init) only now.
    cudaGridDependencySynchronize();

    // per-thread table lookups (id exact: one-hot value is exactly 1.0)
    float vb = (float)vbase;
    int kbase = (tk4 & 1) * 4;       // even chunk -> k0..3, odd -> k4..7
    float s0 = 0.f, s1 = 0.f;
    int id;
    float2 g;
    id = (int)(fmaf(vb, w0, f0) + 0.5f); g = g_table[(kbase + 0) * VV + id];
    s0 = fmaf(w0, g.x, s0); s1 = fmaf(w0, g.y, s1);
    id = (int)(fmaf(vb, w1, f1) + 0.5f); g = g_table[(kbase + 1) * VV + id];
    s0 = fmaf(w1, g.x, s0); s1 = fmaf(w1, g.y, s1);
    id = (int)(fmaf(vb, w2, f2) + 0.5f); g = g_table[(kbase + 2) * VV + id];
    s0 = fmaf(w2, g.x, s0); s1 = fmaf(w2, g.y, s1);
    id = (int)(fmaf(vb, w3, f3) + 0.5f); g = g_table[(kbase + 3) * VV + id];
    s0 = fmaf(w3, g.x, s0); s1 = fmaf(w3, g.y, s1);

    __shared__ float2 ss[VS][TK4];
    ss[vseg][tk4] = make_float2(s0, s1);
    __syncthreads();

    if (tid < TK4) {                  // lanes 0..21 of warp 0
        float a0 = 0.f, a1 = 0.f;
#pragma unroll
        for (int s = 0; s < VS; s++) {   // fixed order -> deterministic
            float2 p = ss[s][tid];
            a0 += p.x; a1 += p.y;
        }
        // merge k0..3 half (even lane) with k4..7 half (odd lane)
        const unsigned mask = 0x003FFFFFu;
        a0 += __shfl_xor_sync(mask, a0, 1);
        a1 += __shfl_xor_sync(mask, a1, 1);

        if ((tid & 1) == 0) {
            int t = tid >> 1;
            atomicAdd(&out[b * (2 * TT) + t],      a0);
            atomicAdd(&out[b * (2 * TT) + TT + t], a1);
        }
    }
}

extern "C" void kernel_launch(void* const* d_in, const int* in_sizes, int n_in,
                              void* d_out, int out_size) {
    const float* x         = (const float*)d_in[0];   // (B, V, T, K)  46137344
    const float* scanner_w = (const float*)d_in[1];   // (N, V, K)     16384
    const float* hidden_w  = (const float*)d_in[2];   // (K*H, N)      16320
    const float* out_w     = (const float*)d_in[3];   // (2, K*H)      4080
    const float* out_bias  = (const float*)d_in[4];   // (2,)          2
    float* out = (float*)d_out;                       // (B, 2, T)     45056

    precompute_table<<<256, 256>>>(scanner_w, hidden_w, out_w, out_bias, out);

    // Secondary launch with programmatic dependent launch: its load loop
    // overlaps the precompute kernel; epilogue grid-dep-syncs before using
    // g_table / out.
    cudaLaunchConfig_t cfg = {};
    cfg.gridDim  = dim3(2 * BB);
    cfg.blockDim = dim3(176);
    cfg.dynamicSmemBytes = 0;
    cfg.stream = 0;
    cudaLaunchAttribute attrs[1];
    attrs[0].id = cudaLaunchAttributeProgrammaticStreamSerialization;
    attrs[0].val.programmaticStreamSerializationAllowed = 1;
    cfg.attrs = attrs;
    cfg.numAttrs = 1;
    cudaLaunchKernelEx(&cfg, scanner_stream, x, out);
}